// round 12
// baseline (speedup 1.0000x reference)
#include <cuda_runtime.h>

#define NN 256
#define BB 64
#define FBIG 1e8f
#define NBIG (-1e8f)
#define K2   144.269504089f     // (1/gamma) * log2(e), gamma = 0.01
#define GLN2 0.006931471806f    // gamma * ln(2)
#define TT   384                // 48 chunks x 8 iters (>= 383 needed)
#define FULL 0xffffffffu

// R scratch, time-major: idx = t*128 + V (V = virtual lane = 2-row group).
// Forward STG and backward mirror LDG are warp-contiguous. 25 MB -> L2.
__device__ float2 g_R2[BB * TT * 128];
__device__ float g_partV[BB];
__device__ float g_partE[BB];
__device__ unsigned g_ticket = 0;

__device__ __forceinline__ float ex2(float x) { float r; asm("ex2.approx.f32 %0, %1;" : "=f"(r) : "f"(x)); return r; }
__device__ __forceinline__ float lg2(float x) { float r; asm("lg2.approx.f32 %0, %1;" : "=f"(r) : "f"(x)); return r; }

__global__ __launch_bounds__(128, 1) void dilate_fb_kernel(
    const float* __restrict__ y_pred,
    const float* __restrict__ y_true,
    float* __restrict__ out)
{
    __shared__ float s_o[NN], s_t[NN];
    __shared__ float s_fh[2][3];          // fwd handoff, parity double-buffered
    __shared__ float s_he[2][3], s_hr[2][3];  // bwd handoffs (E, R)
    __shared__ float s_red[4];
    __shared__ float s_vnn;
    __shared__ int   s_last;

    const int b   = blockIdx.x;
    const int tid = threadIdx.x;      // virtual lane V; owns rows 2V+1, 2V+2
    const int w   = tid >> 5;
    const int l   = tid & 31;

    for (int x = tid; x < NN; x += 128) {
        s_o[x] = y_pred[b * NN + x];
        s_t[x] = y_true[b * NN + x];
    }
    __syncthreads();

    const float ti0 = s_t[2 * tid];
    const float ti1 = s_t[2 * tid + 1];
    float2* __restrict__ Rb = g_R2 + (size_t)b * (TT * 128);

    // ========= FORWARD: (m,w) soft-min, 2 rows/lane, 128-lane ladder =========
    // virtual lane V at iter t computes col q = t-V+1 for rows 2V+1, 2V+2.
    {
        float mm0 = FBIG, mm1 = FBIG, ww0 = 1.0f, ww1 = 1.0f;
        float R0 = FBIG, R1 = FBIG;
        float shA = FBIG, shB = FBIG;   // intra-warp pipeline (lane l-1 folded row-2)
        float lzu = FBIG, lzd = FBIG;   // cross-warp pipeline (lane 0 of w>0)

        for (int c = 0; c < TT / 8; ++c) {
            float o_pre[8];
            #pragma unroll
            for (int k = 0; k < 8; ++k) {
                int x = c * 8 + k - tid;
                x = min(max(x, 0), NN - 1);
                o_pre[k] = s_o[x];
            }
            #pragma unroll
            for (int k = 0; k < 8; ++k) {
                const int t = c * 8 + k;
                const bool act   = (unsigned)(t - tid) < NN;
                const bool first = (t == tid);
                if (first) { mm0 = FBIG; mm1 = FBIG; ww0 = 1.0f; ww1 = 1.0f; }
                float up, dg;
                if (l == 0) { up = (w == 0) ? FBIG : lzu; dg = (w == 0) ? FBIG : lzd; }
                else        { up = shA;                    dg = shB; }
                if (first) dg = (tid == 0) ? 0.0f : FBIG;   // V[0][0]=0 boundary
                float oj = o_pre[k];
                // row0 (up/diag folded, weight 1)
                float ms0 = fminf(mm0, fminf(up, dg));
                float k0  = ms0 * K2;
                float nw0 = fmaf(ww0, ex2(fmaf(-K2, mm0, k0)),
                                 ex2(fmaf(-K2, up, k0)) + ex2(fmaf(-K2, dg, k0)));
                float d0  = ti0 - oj;
                float nm0 = fmaf(d0, d0, ms0);
                // row1: up=(nm0,nw0) cur, diag=(mm0,ww0) old
                float ms1 = fminf(mm1, fminf(nm0, mm0));
                float k1  = ms1 * K2;
                float nw1 = fmaf(ww1, ex2(fmaf(-K2, mm1, k1)),
                            fmaf(nw0, ex2(fmaf(-K2, nm0, k1)),
                                 ww0 * ex2(fmaf(-K2, mm0, k1))));
                float d1  = ti1 - oj;
                float nm1 = fmaf(d1, d1, ms1);
                // fold (off the m-chain)
                R0 = fmaf(-GLN2, lg2(nw0), nm0);
                R1 = fmaf(-GLN2, lg2(nw1), nm1);
                if (act) {
                    Rb[t * 128 + tid] = make_float2(R0, R1);
                    if (tid == 127 && t == NN + 126) s_vnn = R1;   // V[N][N]
                }
                float hp = act ? R1 : FBIG;
                float sh = __shfl_up_sync(FULL, hp, 1);
                shB = shA; shA = sh;
                if (l == 31 && w < 3) s_fh[t & 1][w] = hp;
                __syncthreads();
                if (w > 0) { lzd = lzu; lzu = s_fh[t & 1][w - 1]; }
                mm0 = nm0; ww0 = nw0; mm1 = nm1; ww1 = nw1;
            }
            // renormalize every 8 cols (w <= 3^8): m <- folded V, w <- 1
            mm0 = R0; mm1 = R1; ww0 = 1.0f; ww1 = 1.0f;
        }
    }

    // ========= BACKWARD: mirrored forward, 2 rows/lane =========
    // Reversed p=N+1-i, q'=N+1-j; lane V owns p-rows 2V+1,2V+2 = orig group
    // 127-V (component swap). R for reversed iter t: (NN+126-t)*128 + (127-V).
    float sumE = 0.0f;
    {
        const float tP0 = s_t[255 - 2 * tid];
        const float tP1 = s_t[254 - 2 * tid];
        const float tU  = s_t[min(256 - 2 * tid, 255)];   // T'(p0-1); unused V==0

        float e0 = 0, e1 = 0, r0 = NBIG, r1 = NBIG;
        float shEA = 0, shEB = 0, shRA = NBIG, shRB = NBIG;
        float lzEu = 0, lzEd = 0, lzRu = NBIG, lzRd = NBIG;
        float oqm1 = 0.0f;
        const int bwoff = 127 - tid;
        float2 rc[8], rn[8];

        #pragma unroll
        for (int k = 0; k < 8; ++k) {   // prefetch chunk 0
            int t = k; bool a = (unsigned)(t - tid) < NN;
            rc[k] = a ? __ldg(Rb + (NN + 126 - t) * 128 + bwoff)
                      : make_float2(NBIG, NBIG);
        }

        for (int c = 0; c < TT / 8; ++c) {
            if (c + 1 < TT / 8) {       // prefetch next chunk (overlaps compute)
                #pragma unroll
                for (int k = 0; k < 8; ++k) {
                    int t = (c + 1) * 8 + k; bool a = (unsigned)(t - tid) < NN;
                    rn[k] = a ? __ldg(Rb + (NN + 126 - t) * 128 + bwoff)
                              : make_float2(NBIG, NBIG);
                }
            }
            float o_pre[8];
            #pragma unroll
            for (int k = 0; k < 8; ++k) {
                int x = NN - 1 - (c * 8 + k - tid);
                x = min(max(x, 0), NN - 1);
                o_pre[k] = s_o[x];
            }
            #pragma unroll
            for (int k = 0; k < 8; ++k) {
                const int t = c * 8 + k;
                const bool act   = (unsigned)(t - tid) < NN;
                const bool first = (t == tid);
                if (first) { e0 = 0; e1 = 0; r0 = NBIG; r1 = NBIG; }
                float Eu, Ru, Ed, Rd;
                if (l == 0) { Eu = (w == 0) ? 0.0f : lzEu; Ru = (w == 0) ? NBIG : lzRu;
                              Ed = (w == 0) ? 0.0f : lzEd; Rd = (w == 0) ? NBIG : lzRd; }
                else        { Eu = shEA; Ru = shRA; Ed = shEB; Rd = shRB; }
                if (first) { Ed = 0.0f; Rd = NBIG; }
                float oq = o_pre[k];
                float2 Rc = rc[k];
                float Rc0 = Rc.y, Rc1 = Rc.x;   // component swap (row r <-> 1-r)
                // row0 (p0)
                float dU0 = tU - oq, dL0 = tP0 - oqm1, dD0 = tU - oqm1;
                float ne0 = fmaf(ex2(fmaf(-dU0, dU0, Ru - Rc0) * K2), Eu,
                            fmaf(ex2(fmaf(-dL0, dL0, r0 - Rc0) * K2), e0,
                                 ex2(fmaf(-dD0, dD0, Rd - Rc0) * K2) * Ed));
                if (tid == 0 && t == 0) ne0 = 1.0f;   // E[N][N]
                // row1: up=(Rc0,ne0) cur; diag=(r0,e0) old
                float dU1 = tP0 - oq, dL1 = tP1 - oqm1, dD1 = tP0 - oqm1;
                float ne1 = fmaf(ex2(fmaf(-dU1, dU1, Rc0 - Rc1) * K2), ne0,
                            fmaf(ex2(fmaf(-dL1, dL1, r1 - Rc1) * K2), e1,
                                 ex2(fmaf(-dD1, dD1, r0 - Rc1) * K2) * e0));
                if (!act) { ne0 = 0; ne1 = 0; Rc0 = NBIG; Rc1 = NBIG; }
                if (act) {
                    float wq = (float)(t - 3 * tid);    // (i-j) for row0
                    sumE = fmaf(ne0, wq * wq, sumE);
                    float w1_ = wq - 1.0f;
                    sumE = fmaf(ne1, w1_ * w1_, sumE);
                }
                float sE = __shfl_up_sync(FULL, ne1, 1);
                float sR = __shfl_up_sync(FULL, Rc1, 1);
                shEB = shEA; shEA = sE;
                shRB = shRA; shRA = sR;
                if (l == 31 && w < 3) { s_he[t & 1][w] = ne1; s_hr[t & 1][w] = Rc1; }
                __syncthreads();
                if (w > 0) { lzEd = lzEu; lzRd = lzRu;
                             lzEu = s_he[t & 1][w - 1]; lzRu = s_hr[t & 1][w - 1]; }
                e0 = ne0; e1 = ne1; r0 = Rc0; r1 = Rc1; oqm1 = oq;
            }
            #pragma unroll
            for (int k = 0; k < 8; ++k) rc[k] = rn[k];
        }
    }

    // ---- reduce sum(E * omega) ----
    #pragma unroll
    for (int off = 16; off > 0; off >>= 1)
        sumE += __shfl_down_sync(FULL, sumE, off);
    if (l == 0) s_red[w] = sumE;
    __syncthreads();

    if (tid == 0) {
        g_partV[b] = s_vnn;
        g_partE[b] = s_red[0] + s_red[1] + s_red[2] + s_red[3];
        __threadfence();
        unsigned tk = atomicAdd(&g_ticket, 1u);
        s_last = (tk == BB - 1) ? 1 : 0;
    }
    __syncthreads();
    if (s_last && tid < 32) {
        __threadfence();
        float sv = __ldcg(&g_partV[tid]) + __ldcg(&g_partV[tid + 32]);
        float se = __ldcg(&g_partE[tid]) + __ldcg(&g_partE[tid + 32]);
        #pragma unroll
        for (int off = 16; off > 0; off >>= 1) {
            sv += __shfl_down_sync(FULL, sv, off);
            se += __shfl_down_sync(FULL, se, off);
        }
        if (tid == 0) {
            float loss_shape    = sv * (1.0f / (float)BB);
            float loss_temporal = se * (1.0f / ((float)BB * (float)(NN * NN)));
            out[0] = 0.5f * loss_shape + 0.5f * loss_temporal;
            g_ticket = 0;   // reset for graph replay
        }
    }
}

extern "C" void kernel_launch(void* const* d_in, const int* in_sizes, int n_in,
                              void* d_out, int out_size) {
    const float* y_pred = (const float*)d_in[0];
    const float* y_true = (const float*)d_in[1];
    dilate_fb_kernel<<<BB, 128>>>(y_pred, y_true, (float*)d_out);
}

// round 13
// speedup vs baseline: 1.3596x; 1.3596x over previous
#include <cuda_runtime.h>

#define NN 256
#define BB 64
#define FBIG 1e8f
#define K2   144.269504089f     // (1/gamma) * log2(e), gamma = 0.01
#define GLN2 0.006931471806f    // gamma * ln(2)
#define TT   320                // 40 chunks x 8 iters (>= 319 needed)
#define FULL 0xffffffffu

// Softmin-weight scratch, time-major: per (iter t, virtual lane V) two float4:
//   A = (wu0, wl0, wu1, wl1), B = (wu2, wl2, wu3, wl3)   [rows 4V+1..4V+4]
// wd = 1 - wu - wl (softmax weights sum to 1). Backward reads the mirror slot
// (318-t, 63-V) with row r <-> component 3-r. 42 MB -> L2-resident.
__device__ float4 g_W[BB * TT * 64 * 2];
__device__ float g_partV[BB];
__device__ float g_partE[BB];
__device__ unsigned g_ticket = 0;

__device__ __forceinline__ float ex2(float x) { float r; asm("ex2.approx.f32 %0, %1;" : "=f"(r) : "f"(x)); return r; }
__device__ __forceinline__ float lg2(float x) { float r; asm("lg2.approx.f32 %0, %1;" : "=f"(r) : "f"(x)); return r; }
__device__ __forceinline__ float rcpa(float x){ float r; asm("rcp.approx.f32 %0, %1;" : "=f"(r) : "f"(x)); return r; }

__global__ __launch_bounds__(64, 1) void dilate_fb_kernel(
    const float* __restrict__ y_pred,
    const float* __restrict__ y_true,
    float* __restrict__ out)
{
    __shared__ float s_o[NN], s_t[NN];
    __shared__ float s_fm[2], s_fw[2];      // fwd cross-warp handoff (raw m,w), parity
    __shared__ float s_hu[2], s_hd[2];      // bwd cross-warp handoff (pu, pd), parity
    __shared__ float s_red[2];
    __shared__ float s_vnn;
    __shared__ int   s_last;

    const int b   = blockIdx.x;
    const int tid = threadIdx.x;      // virtual lane V; owns rows 4V+1..4V+4
    const int w   = tid >> 5;
    const int l   = tid & 31;

    for (int x = tid; x < NN; x += 64) {
        s_o[x] = y_pred[b * NN + x];
        s_t[x] = y_true[b * NN + x];
    }
    __syncthreads();

    const float ti0 = s_t[4 * tid];
    const float ti1 = s_t[4 * tid + 1];
    const float ti2 = s_t[4 * tid + 2];
    const float ti3 = s_t[4 * tid + 3];
    float4* __restrict__ Wb = g_W + (size_t)b * (TT * 64 * 2);

    // ===== FORWARD: (m,w) soft-min, 4 rows/lane; emits normalized weights =====
    // virtual lane V at iter t computes col q = t-V+1 for rows 4V+1..4V+4.
    {
        float mm0 = FBIG, mm1 = FBIG, mm2 = FBIG, mm3 = FBIG;
        float ww0 = 1.0f, ww1 = 1.0f, ww2 = 1.0f, ww3 = 1.0f;
        float shAm = FBIG, shAw = 1.0f, shBm = FBIG, shBw = 1.0f;
        float lzum = FBIG, lzuw = 1.0f, lzdm = FBIG, lzdw = 1.0f;

        for (int c = 0; c < TT / 8; ++c) {
            float o_pre[8];
            #pragma unroll
            for (int k = 0; k < 8; ++k) {
                int x = c * 8 + k - tid;
                x = min(max(x, 0), NN - 1);
                o_pre[k] = s_o[x];
            }
            #pragma unroll
            for (int k = 0; k < 8; ++k) {
                const int t = c * 8 + k;
                const bool act   = (unsigned)(t - tid) < NN;
                const bool first = (t == tid);
                if (first) { mm0 = FBIG; mm1 = FBIG; mm2 = FBIG; mm3 = FBIG;
                             ww0 = 1.0f; ww1 = 1.0f; ww2 = 1.0f; ww3 = 1.0f; }
                float um, uw, dm, dw;
                if (l == 0) { um = (w == 0) ? FBIG : lzum; uw = (w == 0) ? 1.0f : lzuw;
                              dm = (w == 0) ? FBIG : lzdm; dw = (w == 0) ? 1.0f : lzdw; }
                else        { um = shAm; uw = shAw; dm = shBm; dw = shBw; }
                if (first) { dm = (tid == 0) ? 0.0f : FBIG; dw = 1.0f; }   // V[0][0]=0
                const float oj = o_pre[k];
                float wu_s0, wl_s0, wu_s1, wl_s1, wu_s2, wl_s2, wu_s3, wl_s3;
                // row0
                {
                    float ms = fminf(mm0, fminf(um, dm));
                    float kk = ms * K2;
                    float tl = ww0 * ex2(fmaf(-K2, mm0, kk));
                    float tu = uw  * ex2(fmaf(-K2, um,  kk));
                    float td = dw  * ex2(fmaf(-K2, dm,  kk));
                    float nw = tl + tu + td;
                    float rc = rcpa(nw);
                    wu_s0 = tu * rc; wl_s0 = tl * rc;
                    float d = ti0 - oj;
                    float nm = fmaf(d, d, ms);
                    dm = mm0; dw = ww0;          // next row's diag = old state
                    mm0 = nm; ww0 = nw;
                    um = nm;  uw = nw;           // next row's up = new state
                }
                // row1
                {
                    float ms = fminf(mm1, fminf(um, dm));
                    float kk = ms * K2;
                    float tl = ww1 * ex2(fmaf(-K2, mm1, kk));
                    float tu = uw  * ex2(fmaf(-K2, um,  kk));
                    float td = dw  * ex2(fmaf(-K2, dm,  kk));
                    float nw = tl + tu + td;
                    float rc = rcpa(nw);
                    wu_s1 = tu * rc; wl_s1 = tl * rc;
                    float d = ti1 - oj;
                    float nm = fmaf(d, d, ms);
                    dm = mm1; dw = ww1;
                    mm1 = nm; ww1 = nw;
                    um = nm;  uw = nw;
                }
                // row2
                {
                    float ms = fminf(mm2, fminf(um, dm));
                    float kk = ms * K2;
                    float tl = ww2 * ex2(fmaf(-K2, mm2, kk));
                    float tu = uw  * ex2(fmaf(-K2, um,  kk));
                    float td = dw  * ex2(fmaf(-K2, dm,  kk));
                    float nw = tl + tu + td;
                    float rc = rcpa(nw);
                    wu_s2 = tu * rc; wl_s2 = tl * rc;
                    float d = ti2 - oj;
                    float nm = fmaf(d, d, ms);
                    dm = mm2; dw = ww2;
                    mm2 = nm; ww2 = nw;
                    um = nm;  uw = nw;
                }
                // row3
                {
                    float ms = fminf(mm3, fminf(um, dm));
                    float kk = ms * K2;
                    float tl = ww3 * ex2(fmaf(-K2, mm3, kk));
                    float tu = uw  * ex2(fmaf(-K2, um,  kk));
                    float td = dw  * ex2(fmaf(-K2, dm,  kk));
                    float nw = tl + tu + td;
                    float rc = rcpa(nw);
                    wu_s3 = tu * rc; wl_s3 = tl * rc;
                    float d = ti3 - oj;
                    float nm = fmaf(d, d, ms);
                    mm3 = nm; ww3 = nw;
                }
                if (act) {
                    float4* p = Wb + (((t << 6) + tid) << 1);
                    p[0] = make_float4(wu_s0, wl_s0, wu_s1, wl_s1);
                    p[1] = make_float4(wu_s2, wl_s2, wu_s3, wl_s3);
                    if (tid == 63 && t == NN + 62)
                        s_vnn = fmaf(-GLN2, lg2(ww3), mm3);     // V[N][N]
                }
                float hm = act ? mm3 : FBIG;
                float hw = act ? ww3 : 1.0f;
                shBm = shAm; shBw = shAw;
                shAm = __shfl_up_sync(FULL, hm, 1);
                shAw = __shfl_up_sync(FULL, hw, 1);
                if (l == 31 && w == 0) { s_fm[t & 1] = hm; s_fw[t & 1] = hw; }
                __syncthreads();
                if (w == 1) { lzdm = lzum; lzdw = lzuw;
                              lzum = s_fm[t & 1]; lzuw = s_fw[t & 1]; }
            }
            // renormalize every 8 cols: m <- folded V, w <- 1 (bounds w)
            mm0 = fmaf(-GLN2, lg2(ww0), mm0); ww0 = 1.0f;
            mm1 = fmaf(-GLN2, lg2(ww1), mm1); ww1 = 1.0f;
            mm2 = fmaf(-GLN2, lg2(ww2), mm2); ww2 = 1.0f;
            mm3 = fmaf(-GLN2, lg2(ww3), mm3); ww3 = 1.0f;
        }
    }

    // ===== BACKWARD: weight-flow, MUFU-free. E = pu_in + pl_own + pd_in ======
    // Mirrored coords: lane V, iter t -> orig rows i = 256-4V-r, col j = 256-(t-V).
    // Weights of this cell: forward slot (318-t, 63-V), row r <-> component 3-r.
    float sumE = 0.0f;
    {
        float pl0 = 0, pl1 = 0, pl2 = 0, pl3 = 0;       // E*wl from prev iter
        float pdo0 = 0, pdo1 = 0, pdo2 = 0, pdo3 = 0;   // E*wd from prev iter
        float shApu = 0, shApd = 0, shBpd = 0;
        float lz_u = 0, lz_d = 0, lz_dHold = 0;
        float4 rcA[4], rcB[4], rnA[4], rnB[4];

        #pragma unroll
        for (int k = 0; k < 4; ++k) {   // prefetch chunk 0
            int t = k; bool a = (unsigned)(t - tid) < NN;
            const float4* p = Wb + (((((318 - t) << 6)) + (63 - tid)) << 1);
            rcA[k] = a ? __ldg(p)     : make_float4(0, 0, 0, 0);
            rcB[k] = a ? __ldg(p + 1) : make_float4(0, 0, 0, 0);
        }

        for (int c = 0; c < TT / 4; ++c) {
            if (c + 1 < TT / 4) {       // prefetch next chunk (overlaps compute)
                #pragma unroll
                for (int k = 0; k < 4; ++k) {
                    int t = (c + 1) * 4 + k; bool a = (unsigned)(t - tid) < NN;
                    const float4* p = Wb + (((((318 - t) << 6)) + (63 - tid)) << 1);
                    rnA[k] = a ? __ldg(p)     : make_float4(0, 0, 0, 0);
                    rnB[k] = a ? __ldg(p + 1) : make_float4(0, 0, 0, 0);
                }
            }
            #pragma unroll
            for (int k = 0; k < 4; ++k) {
                const int t = c * 4 + k;
                const bool act   = (unsigned)(t - tid) < NN;
                const bool first = (t == tid);
                if (first) { pl0 = pl1 = pl2 = pl3 = 0.0f;
                             pdo0 = pdo1 = pdo2 = pdo3 = 0.0f; }
                float pu_in, pd_in;
                if (l == 0) { pu_in = (w == 0) ? 0.0f : lz_u;
                              pd_in = (w == 0) ? 0.0f : lz_d; }
                else        { pu_in = shApu; pd_in = shBpd; }
                if (first) pd_in = 0.0f;
                const float4 A = rcA[k], B = rcB[k];
                // row r <-> fwd component 3-r:
                const float wu0 = B.z, wl0_ = B.w;   // r0
                const float wu1 = B.x, wl1_ = B.y;   // r1
                const float wu2 = A.z, wl2_ = A.w;   // r2
                const float wu3 = A.x, wl3_ = A.y;   // r3
                const float wqb = (float)(t - 5 * tid);   // (i-j) for row0
                float pu3 = 0.0f, pd3 = 0.0f;
                // row0
                {
                    float E = pu_in + pl0 + pd_in;
                    if (tid == 0 && t == 0) E = 1.0f;       // E[N][N]
                    float wd = 1.0f - wu0 - wl0_;
                    float pu = E * wu0, pd = E * wd, pln = E * wl0_;
                    if (!act) { pu = 0; pd = 0; pln = 0; }
                    else sumE = fmaf(E, wqb * wqb, sumE);
                    pd_in = pdo0; pdo0 = pd; pl0 = pln; pu_in = pu;
                }
                // row1
                {
                    float E = pu_in + pl1 + pd_in;
                    float wd = 1.0f - wu1 - wl1_;
                    float pu = E * wu1, pd = E * wd, pln = E * wl1_;
                    if (!act) { pu = 0; pd = 0; pln = 0; }
                    else { float wq = wqb - 1.0f; sumE = fmaf(E, wq * wq, sumE); }
                    pd_in = pdo1; pdo1 = pd; pl1 = pln; pu_in = pu;
                }
                // row2
                {
                    float E = pu_in + pl2 + pd_in;
                    float wd = 1.0f - wu2 - wl2_;
                    float pu = E * wu2, pd = E * wd, pln = E * wl2_;
                    if (!act) { pu = 0; pd = 0; pln = 0; }
                    else { float wq = wqb - 2.0f; sumE = fmaf(E, wq * wq, sumE); }
                    pd_in = pdo2; pdo2 = pd; pl2 = pln; pu_in = pu;
                }
                // row3
                {
                    float E = pu_in + pl3 + pd_in;
                    float wd = 1.0f - wu3 - wl3_;
                    float pu = E * wu3, pd = E * wd, pln = E * wl3_;
                    if (!act) { pu = 0; pd = 0; pln = 0; }
                    else { float wq = wqb - 3.0f; sumE = fmaf(E, wq * wq, sumE); }
                    pdo3 = pd; pl3 = pln;
                    pu3 = pu; pd3 = pd;
                }
                shBpd = shApd;
                shApd = __shfl_up_sync(FULL, pd3, 1);
                shApu = __shfl_up_sync(FULL, pu3, 1);
                if (l == 31 && w == 0) { s_hu[t & 1] = pu3; s_hd[t & 1] = pd3; }
                __syncthreads();
                if (w == 1) { lz_d = lz_dHold;
                              lz_dHold = s_hd[t & 1]; lz_u = s_hu[t & 1]; }
            }
            #pragma unroll
            for (int k = 0; k < 4; ++k) { rcA[k] = rnA[k]; rcB[k] = rnB[k]; }
        }
    }

    // ---- reduce sum(E * omega) ----
    #pragma unroll
    for (int off = 16; off > 0; off >>= 1)
        sumE += __shfl_down_sync(FULL, sumE, off);
    if (l == 0) s_red[w] = sumE;
    __syncthreads();

    if (tid == 0) {
        g_partV[b] = s_vnn;
        g_partE[b] = s_red[0] + s_red[1];
        __threadfence();
        unsigned tk = atomicAdd(&g_ticket, 1u);
        s_last = (tk == BB - 1) ? 1 : 0;
    }
    __syncthreads();
    if (s_last && tid < 32) {
        __threadfence();
        float sv = __ldcg(&g_partV[tid]) + __ldcg(&g_partV[tid + 32]);
        float se = __ldcg(&g_partE[tid]) + __ldcg(&g_partE[tid + 32]);
        #pragma unroll
        for (int off = 16; off > 0; off >>= 1) {
            sv += __shfl_down_sync(FULL, sv, off);
            se += __shfl_down_sync(FULL, se, off);
        }
        if (tid == 0) {
            float loss_shape    = sv * (1.0f / (float)BB);
            float loss_temporal = se * (1.0f / ((float)BB * (float)(NN * NN)));
            out[0] = 0.5f * loss_shape + 0.5f * loss_temporal;
            g_ticket = 0;   // reset for graph replay
        }
    }
}

extern "C" void kernel_launch(void* const* d_in, const int* in_sizes, int n_in,
                              void* d_out, int out_size) {
    const float* y_pred = (const float*)d_in[0];
    const float* y_true = (const float*)d_in[1];
    dilate_fb_kernel<<<BB, 64>>>(y_pred, y_true, (float*)d_out);
}